// round 14
// baseline (speedup 1.0000x reference)
#include <cuda_runtime.h>
#include <math.h>

#define NB 8
#define NH 512
#define NW 512
#define NP 32
#define HWC (NH*NW)
#define EPSF 1e-8f
#define INV2BW2 50.0f
#define NSEG 32
#define SEGROWS 16
#define SDSTRIDE 544        /* >= 512 + 32 skew: max skewed index 542 */
#define NBLK (NB*NSEG)      /* 256 */

typedef unsigned long long u64;

/* ---------------- scratch (device globals) ---------------- */
__device__ float g_ex[NB*NP*NW];
__device__ float g_ey[NB*NP*NH];
__device__ float g_colseg[NB*NSEG*NW];   /* 512 KB, L2-resident */
__device__ u64 g_tsum_fx[NB];            /* fixed-point 2^32 accumulators */
__device__ u64 g_psum_fx[NB];
__device__ u64 g_kl_fx, g_ew_fx, g_eh_fx;
__device__ u64 g_pkP[NB], g_pkT[NB];     /* packed argmax keys */
__device__ unsigned g_arr0[NB], g_arr1[NB], g_done;

/* fixed-point (scale 2^32), exact integer atomics -> deterministic */
__device__ __forceinline__ u64 to_fx(float x) {
    return (u64)__double2ll_rn((double)x * 4294967296.0);
}
__device__ __forceinline__ float from_fx(u64 v) {
    return (float)((double)(long long)v * (1.0/4294967296.0));
}

/* packed f32x2 ops (Blackwell) */
__device__ __forceinline__ u64 fma2(u64 a, u64 b, u64 c) {
    u64 d; asm("fma.rn.f32x2 %0, %1, %2, %3;" : "=l"(d) : "l"(a), "l"(b), "l"(c)); return d;
}
__device__ __forceinline__ u64 add2(u64 a, u64 b) {
    u64 d; asm("add.rn.f32x2 %0, %1, %2;" : "=l"(d) : "l"(a), "l"(b)); return d;
}
__device__ __forceinline__ u64 pack2(float lo, float hi) {
    u64 d; asm("mov.b64 %0, {%1, %2};" : "=l"(d) : "f"(lo), "f"(hi)); return d;
}
__device__ __forceinline__ float hadd2(u64 v) {
    float lo, hi; asm("mov.b64 {%0, %1}, %2;" : "=f"(lo), "=f"(hi) : "l"(v)); return lo + hi;
}

/* argmax key: val>=0 so float bits monotone; ~fid gives min-idx tie-break */
__device__ __forceinline__ u64 mkkey(float v, int fid) {
    return ((u64)__float_as_uint(v) << 32) | (u64)(0xFFFFFFFFu - (unsigned)fid);
}

__global__ __launch_bounds__(512, 2) void k_all(const float* __restrict__ pred,
                                                const float* __restrict__ pts,
                                                const float* __restrict__ mask,
                                                float* __restrict__ out, int out_size) {
    int blk = blockIdx.x;                 /* b*NSEG+seg == factor index b*NP+n */
    int b = blk >> 5, seg = blk & 31;
    int w = threadIdx.x, lane = w & 31, wid = w >> 5;

    __shared__ __align__(16) float sEy[SEGROWS*NP];
    __shared__ float sD[SEGROWS*SDSTRIDE];
    __shared__ float sredA[16], sredB[16], sredC[16];
    __shared__ u64   sredK[16], sredK2[16];
    __shared__ float sNorm[4];            /* mInvSp, cSp, mInvSt, cSt */
    __shared__ int   sLast;

    /* ===== PHASE A: own point's factors + 1-D sums + own-tile psum ===== */
    {
        const float4* p4 = (const float4*)(pred + (b*NH + seg*SEGROWS)*NW);
        float4 q0 = p4[w], q1 = p4[w+512], q2 = p4[w+1024], q3 = p4[w+1536];

        float px = pts[blk*2 + 0];
        float py = pts[blk*2 + 1];
        float c  = (float)w * (1.0f/511.0f);
        float dx = c - px, dy = c - py;
        float ex = __expf(-dx*dx*INV2BW2);
        float ey = __expf(-dy*dy*INV2BW2);
        g_ex[blk*NW + w] = ex;
        g_ey[blk*NH + w] = ey;

        float ps = ((q0.x+q0.y)+(q0.z+q0.w)) + ((q1.x+q1.y)+(q1.z+q1.w))
                 + ((q2.x+q2.y)+(q2.z+q2.w)) + ((q3.x+q3.y)+(q3.z+q3.w));
        float vx = ex, vy = ey;
#pragma unroll
        for (int off = 16; off; off >>= 1) {
            vx += __shfl_xor_sync(~0u, vx, off);
            vy += __shfl_xor_sync(~0u, vy, off);
            ps += __shfl_xor_sync(~0u, ps, off);
        }
        if (lane == 0) { sredA[wid] = vx; sredB[wid] = vy; sredC[wid] = ps; }
        __syncthreads();
        if (w == 0) {
            float sx = 0.f, sy = 0.f, sp = 0.f;
#pragma unroll
            for (int j = 0; j < 16; j++) { sx += sredA[j]; sy += sredB[j]; sp += sredC[j]; }
            atomicAdd(&g_tsum_fx[b], to_fx(sx * sy));
            atomicAdd(&g_psum_fx[b], to_fx(sp));
            __threadfence();
            atomicAdd(&g_arr0[b], 1u);
            volatile unsigned* a0 = &g_arr0[b];
            while (*a0 < (unsigned)NSEG) __nanosleep(32);
            __threadfence();
            float ts = from_fx(*(volatile u64*)&g_tsum_fx[b]);
            float pp = from_fx(*(volatile u64*)&g_psum_fx[b]);
            float mm = mask[b];
            float iSp = 1.0f / (mm*pp + (float)HWC*EPSF);
            float iSt = 1.0f / (mm*ts + (float)HWC*EPSF);
            sNorm[0] = mm * iSp;   sNorm[1] = EPSF * iSp;
            sNorm[2] = mm * iSt;   sNorm[3] = EPSF * iSt;
        }
    }
    __syncthreads();

    /* ===== PHASE B: density(FFMA2 x4 chains) + KL + EMD-W + colseg + argmax ===== */
    sEy[(w >> 5)*NP + (w & 31)] = g_ey[(b*NP + (w & 31))*NH + seg*SEGROWS + (w >> 5)];

    u64 rexp[NP/2];
#pragma unroll
    for (int n = 0; n < NP; n += 2)
        rexp[n >> 1] = pack2(g_ex[(b*NP + n)*NW + w], g_ex[(b*NP + n + 1)*NW + w]);
    __syncthreads();

    float mInvSp = sNorm[0], cSp = sNorm[1];
    float mInvSt = sNorm[2], cSt = sNorm[3];

    float klacc = 0.f, ccol = 0.f;
    u64 keyP = 0ull, keyT = 0ull;
    int rowbase = (b*NH + seg*SEGROWS)*NW + w;
    int fid0 = seg*SEGROWS*NW + w;
    int skw = w + (w >> 4);

#pragma unroll 4
    for (int r = 0; r < SEGROWS; r++) {
        float p = __ldg(&pred[rowbase + r*NW]);
        /* density: 8 x LDS.128 -> 16 FFMA2 across 4 chains */
        u64 a0 = 0ull, a1 = 0ull, a2 = 0ull, a3 = 0ull;
#pragma unroll
        for (int q = 0; q < NP/8; q++) {
            ulonglong2 e0 = *(const ulonglong2*)&sEy[r*NP + q*8 + 0];
            ulonglong2 e1 = *(const ulonglong2*)&sEy[r*NP + q*8 + 4];
            a0 = fma2(e0.x, rexp[q*4 + 0], a0);
            a1 = fma2(e0.y, rexp[q*4 + 1], a1);
            a2 = fma2(e1.x, rexp[q*4 + 2], a2);
            a3 = fma2(e1.y, rexp[q*4 + 3], a3);
        }
        float acc = hadd2(add2(add2(a0, a2), add2(a1, a3)));
        float pn = fmaf(p,   mInvSp, cSp);
        float tn = fmaf(acc, mInvSt, cSt);
        float d  = pn - tn;
        sD[r*SDSTRIDE + skw] = d;
        klacc = fmaf(tn, __logf(__fdividef(tn, pn + EPSF)), klacc);
        ccol += d;
        int fid = fid0 + r*NW;
        u64 kp = mkkey(pn, fid); if (kp > keyP) keyP = kp;
        u64 kt = mkkey(tn, fid); if (kt > keyT) keyT = kt;
    }
    g_colseg[blk*NW + w] = ccol;
    __syncthreads();

    /* EMD-W: warp wid scans row wid; lane owns 16 contiguous elems */
    float ewacc = 0.f;
    {
        float vals[16];
        int base = wid*SDSTRIDE + lane*17;
        float s = 0.f;
#pragma unroll
        for (int i = 0; i < 16; i++) { vals[i] = sD[base + i]; s += vals[i]; }
        float incl = s;
#pragma unroll
        for (int off = 1; off < 32; off <<= 1) {
            float u = __shfl_up_sync(~0u, incl, off);
            if (lane >= off) incl += u;
        }
        float run = incl - s;
#pragma unroll
        for (int i = 0; i < 16; i++) { run += vals[i]; ewacc += fabsf(run); }
    }

    /* block reductions: kl + emdw (floats) + both argmax keys (u64), one pass */
    {
        float v1 = klacc, v2 = ewacc;
        u64 kP = keyP, kT = keyT;
#pragma unroll
        for (int off = 16; off; off >>= 1) {
            v1 += __shfl_xor_sync(~0u, v1, off);
            v2 += __shfl_xor_sync(~0u, v2, off);
            u64 oP = __shfl_xor_sync(~0u, kP, off);
            u64 oT = __shfl_xor_sync(~0u, kT, off);
            if (oP > kP) kP = oP;
            if (oT > kT) kT = oT;
        }
        if (lane == 0) { sredA[wid] = v1; sredB[wid] = v2; sredK[wid] = kP; sredK2[wid] = kT; }
        __syncthreads();
        if (w == 0) {
            float s1 = 0.f, s2 = 0.f;
            u64 bP = sredK[0], bT = sredK2[0];
#pragma unroll
            for (int j = 0; j < 16; j++) {
                s1 += sredA[j]; s2 += sredB[j];
                if (j && sredK[j]  > bP) bP = sredK[j];
                if (j && sredK2[j] > bT) bT = sredK2[j];
            }
            atomicAdd(&g_kl_fx, to_fx(s1));
            atomicAdd(&g_ew_fx, to_fx(s2));
            atomicMax(&g_pkP[b], bP);
            atomicMax(&g_pkT[b], bT);
            __threadfence();
            atomicAdd(&g_arr1[b], 1u);
            volatile unsigned* a1p = &g_arr1[b];
            while (*a1p < (unsigned)NSEG) __nanosleep(32);
            __threadfence();
        }
    }
    __syncthreads();

    /* ===== PHASE C: EMD-H from smem tile + L2 carry ===== */
    {
        const float* cs = &g_colseg[(b*NSEG)*NW + w];
        float c0 = 0.f, c1 = 0.f, c2 = 0.f, c3 = 0.f;
#pragma unroll
        for (int s2 = 0; s2 < NSEG; s2 += 4) {
            if (s2 + 0 < seg) c0 += cs[(s2+0)*NW];
            if (s2 + 1 < seg) c1 += cs[(s2+1)*NW];
            if (s2 + 2 < seg) c2 += cs[(s2+2)*NW];
            if (s2 + 3 < seg) c3 += cs[(s2+3)*NW];
        }
        float c = (c0 + c1) + (c2 + c3);
        float acc = 0.f;
#pragma unroll
        for (int r = 0; r < SEGROWS; r++) { c += sD[r*SDSTRIDE + skw]; acc += fabsf(c); }

#pragma unroll
        for (int off = 16; off; off >>= 1) acc += __shfl_xor_sync(~0u, acc, off);
        if (lane == 0) sredA[wid] = acc;
        __syncthreads();
        if (w == 0) {
            float s = 0.f;
#pragma unroll
            for (int j = 0; j < 16; j++) s += sredA[j];
            atomicAdd(&g_eh_fx, to_fx(s));
            __threadfence();
            unsigned t = atomicAdd(&g_done, 1u);
            sLast = (t == (unsigned)(NBLK-1)) ? 1 : 0;
        }
    }
    __syncthreads();

    /* ===== FINALIZE: last-done block only ===== */
    if (sLast && w == 0) {
        __threadfence();
        float loss = from_fx(*(volatile u64*)&g_kl_fx) * (1.0f/(float)NB);
        float emd  = (from_fx(*(volatile u64*)&g_ew_fx) + from_fx(*(volatile u64*)&g_eh_fx))
                     * (0.5f / ((float)NB * (float)HWC));
        int cnt = 0;
        for (int bb = 0; bb < NB; bb++) {
            unsigned fp = 0xFFFFFFFFu - (unsigned)(*(volatile u64*)&g_pkP[bb] & 0xFFFFFFFFull);
            unsigned ft = 0xFFFFFFFFu - (unsigned)(*(volatile u64*)&g_pkT[bb] & 0xFFFFFFFFull);
            float ppx = (float)(fp % NW) * (1.0f/511.0f);
            float ppy = (float)(fp / NW) * (1.0f/511.0f);
            float tpx = (float)(ft % NW) * (1.0f/511.0f);
            float tpy = (float)(ft / NW) * (1.0f/511.0f);
            float dx = ppx - tpx, dy = ppy - tpy;
            if (sqrtf(dx*dx + dy*dy) < 0.1f) cnt++;
        }
        float acc = (float)cnt * (1.0f/(float)NB);
        if (out_size > 0) out[0] = loss;
        if (out_size > 1) out[1] = emd;
        if (out_size > 2) out[2] = acc;
        /* reset state for next graph replay */
        g_kl_fx = 0ull; g_ew_fx = 0ull; g_eh_fx = 0ull;
        g_done = 0u;
#pragma unroll
        for (int bb = 0; bb < NB; bb++) {
            g_tsum_fx[bb] = 0ull; g_psum_fx[bb] = 0ull;
            g_pkP[bb] = 0ull;     g_pkT[bb] = 0ull;
            g_arr0[bb] = 0u;      g_arr1[bb] = 0u;
        }
        __threadfence();
    }
}

extern "C" void kernel_launch(void* const* d_in, const int* in_sizes, int n_in,
                              void* d_out, int out_size) {
    const float* pred = (const float*)d_in[0];   /* [8,512,512] */
    const float* pts  = (const float*)d_in[1];   /* [8,32,2]    */
    const float* mask = (const float*)d_in[2];   /* [8]         */
    float* out = (float*)d_out;

    k_all<<<NBLK, 512>>>(pred, pts, mask, out, out_size);
}

// round 15
// speedup vs baseline: 1.0692x; 1.0692x over previous
#include <cuda_runtime.h>
#include <math.h>

#define NB 8
#define NH 512
#define NW 512
#define NP 32
#define HWC (NH*NW)
#define EPSF 1e-8f
#define INV2BW2 50.0f
#define NSEG 32
#define SEGROWS 16
#define SDSTRIDE 544        /* >= 512 + 32 skew: max skewed index 542 */
#define NBLK (NB*NSEG)      /* 256 */
#define LN2F 0.6931471805599453f

typedef unsigned long long u64;

/* ---------------- scratch (device globals) ---------------- */
__device__ float g_ex[NB*NP*NW];
__device__ float g_ey[NB*NP*NH];
__device__ float g_colseg[NB*NSEG*NW];   /* 512 KB, L2-resident */
__device__ u64 g_tsum_fx[NB];            /* fixed-point 2^32 accumulators */
__device__ u64 g_psum_fx[NB];
__device__ u64 g_kl_fx, g_ew_fx, g_eh_fx;
__device__ u64 g_pkP[NB], g_pkT[NB];     /* packed argmax keys */
__device__ unsigned g_arr0[NB], g_arr1[NB], g_done;

/* fixed-point (scale 2^32), exact integer atomics -> deterministic */
__device__ __forceinline__ u64 to_fx(float x) {
    return (u64)__double2ll_rn((double)x * 4294967296.0);
}
__device__ __forceinline__ float from_fx(u64 v) {
    return (float)((double)(long long)v * (1.0/4294967296.0));
}

/* packed f32x2 ops (Blackwell) */
__device__ __forceinline__ u64 fma2(u64 a, u64 b, u64 c) {
    u64 d; asm("fma.rn.f32x2 %0, %1, %2, %3;" : "=l"(d) : "l"(a), "l"(b), "l"(c)); return d;
}
__device__ __forceinline__ u64 pack2(float lo, float hi) {
    u64 d; asm("mov.b64 %0, {%1, %2};" : "=l"(d) : "f"(lo), "f"(hi)); return d;
}
__device__ __forceinline__ float hadd2(u64 v) {
    float lo, hi; asm("mov.b64 {%0, %1}, %2;" : "=f"(lo), "=f"(hi) : "l"(v)); return lo + hi;
}

/* argmax key: val>=0 so float bits monotone; ~fid gives min-idx tie-break */
__device__ __forceinline__ u64 mkkey(float v, int fid) {
    return ((u64)__float_as_uint(v) << 32) | (u64)(0xFFFFFFFFu - (unsigned)fid);
}

__global__ __launch_bounds__(512, 2) void k_all(const float* __restrict__ pred,
                                                const float* __restrict__ pts,
                                                const float* __restrict__ mask,
                                                float* __restrict__ out, int out_size) {
    int blk = blockIdx.x;                 /* b*NSEG+seg == factor index b*NP+n */
    int b = blk >> 5, seg = blk & 31;
    int w = threadIdx.x, lane = w & 31, wid = w >> 5;

    __shared__ __align__(16) float sEy[SEGROWS*NP];
    __shared__ float sD[SEGROWS*SDSTRIDE];
    __shared__ float sredA[16], sredB[16], sredC[16];
    __shared__ u64   sredK[16], sredK2[16];
    __shared__ float sNorm[4];            /* mInvSp, cSp, mInvSt, cSt */
    __shared__ int   sLast;

    /* ===== PHASE A: own point's factors + 1-D sums + own-tile psum ===== */
    {
        const float4* p4 = (const float4*)(pred + (b*NH + seg*SEGROWS)*NW);
        float4 q0 = p4[w], q1 = p4[w+512], q2 = p4[w+1024], q3 = p4[w+1536];

        float px = pts[blk*2 + 0];
        float py = pts[blk*2 + 1];
        float c  = (float)w * (1.0f/511.0f);
        float dx = c - px, dy = c - py;
        float ex = __expf(-dx*dx*INV2BW2);
        float ey = __expf(-dy*dy*INV2BW2);
        g_ex[blk*NW + w] = ex;
        g_ey[blk*NH + w] = ey;

        float ps = ((q0.x+q0.y)+(q0.z+q0.w)) + ((q1.x+q1.y)+(q1.z+q1.w))
                 + ((q2.x+q2.y)+(q2.z+q2.w)) + ((q3.x+q3.y)+(q3.z+q3.w));
        float vx = ex, vy = ey;
#pragma unroll
        for (int off = 16; off; off >>= 1) {
            vx += __shfl_xor_sync(~0u, vx, off);
            vy += __shfl_xor_sync(~0u, vy, off);
            ps += __shfl_xor_sync(~0u, ps, off);
        }
        if (lane == 0) { sredA[wid] = vx; sredB[wid] = vy; sredC[wid] = ps; }
        __syncthreads();
        if (w == 0) {
            float sx = 0.f, sy = 0.f, sp = 0.f;
#pragma unroll
            for (int j = 0; j < 16; j++) { sx += sredA[j]; sy += sredB[j]; sp += sredC[j]; }
            atomicAdd(&g_tsum_fx[b], to_fx(sx * sy));
            atomicAdd(&g_psum_fx[b], to_fx(sp));
            __threadfence();
            atomicAdd(&g_arr0[b], 1u);
            volatile unsigned* a0 = &g_arr0[b];
            while (*a0 < (unsigned)NSEG) __nanosleep(32);
            __threadfence();
            float ts = from_fx(*(volatile u64*)&g_tsum_fx[b]);
            float pp = from_fx(*(volatile u64*)&g_psum_fx[b]);
            float mm = mask[b];
            float iSp = 1.0f / (mm*pp + (float)HWC*EPSF);
            float iSt = 1.0f / (mm*ts + (float)HWC*EPSF);
            sNorm[0] = mm * iSp;   sNorm[1] = EPSF * iSp;
            sNorm[2] = mm * iSt;   sNorm[3] = EPSF * iSt;
        }
    }
    __syncthreads();

    /* ===== PHASE B: density(FFMA2) + KL(log2) + EMD-W + colseg + argmax ===== */
    sEy[(w >> 5)*NP + (w & 31)] = g_ey[(b*NP + (w & 31))*NH + seg*SEGROWS + (w >> 5)];

    u64 rexp[NP/2];
#pragma unroll
    for (int n = 0; n < NP; n += 2)
        rexp[n >> 1] = pack2(g_ex[(b*NP + n)*NW + w], g_ex[(b*NP + n + 1)*NW + w]);
    __syncthreads();

    float mInvSp = sNorm[0], cSp = sNorm[1];
    float mInvSt = sNorm[2], cSt = sNorm[3];

    float klacc = 0.f, ccol = 0.f;      /* klacc accumulated in log2 domain */
    float apv = -1e30f, atv = -1e30f;
    int   api = 0, ati = 0;
    int rowbase = (b*NH + seg*SEGROWS)*NW + w;
    int fid0 = seg*SEGROWS*NW + w;
    int skw = w + (w >> 4);

#pragma unroll 2
    for (int r = 0; r < SEGROWS; r++) {
        float p = __ldg(&pred[rowbase + r*NW]);
        /* density: 8 x LDS.128 (as 2 f32x2 pairs each) -> 16 FFMA2, 2 chains */
        u64 a0 = 0ull, a1 = 0ull;
#pragma unroll
        for (int q = 0; q < NP/4; q++) {
            ulonglong2 e = *(const ulonglong2*)&sEy[r*NP + q*4];
            a0 = fma2(e.x, rexp[q*2 + 0], a0);
            a1 = fma2(e.y, rexp[q*2 + 1], a1);
        }
        float acc = hadd2(a0) + hadd2(a1);
        float pn = fmaf(p,   mInvSp, cSp);
        float tn = fmaf(acc, mInvSt, cSt);
        float d  = pn - tn;
        sD[r*SDSTRIDE + skw] = d;
        klacc = fmaf(tn, __log2f(__fdividef(tn, pn + EPSF)), klacc);
        ccol += d;
        int fid = fid0 + r*NW;
        if (pn > apv) { apv = pn; api = fid; }
        if (tn > atv) { atv = tn; ati = fid; }
    }
    g_colseg[blk*NW + w] = ccol;
    __syncthreads();

    /* EMD-W: warp wid scans row wid; lane owns 16 contiguous elems */
    float ewacc = 0.f;
    {
        float vals[16];
        int base = wid*SDSTRIDE + lane*17;
        float s = 0.f;
#pragma unroll
        for (int i = 0; i < 16; i++) { vals[i] = sD[base + i]; s += vals[i]; }
        float incl = s;
#pragma unroll
        for (int off = 1; off < 32; off <<= 1) {
            float u = __shfl_up_sync(~0u, incl, off);
            if (lane >= off) incl += u;
        }
        float run = incl - s;
#pragma unroll
        for (int i = 0; i < 16; i++) { run += vals[i]; ewacc += fabsf(run); }
    }

    /* block reductions: kl + emdw (floats) + both argmax keys (u64), one pass */
    {
        float v1 = klacc, v2 = ewacc;
        u64 kP = mkkey(apv, api), kT = mkkey(atv, ati);
#pragma unroll
        for (int off = 16; off; off >>= 1) {
            v1 += __shfl_xor_sync(~0u, v1, off);
            v2 += __shfl_xor_sync(~0u, v2, off);
            u64 oP = __shfl_xor_sync(~0u, kP, off);
            u64 oT = __shfl_xor_sync(~0u, kT, off);
            if (oP > kP) kP = oP;
            if (oT > kT) kT = oT;
        }
        if (lane == 0) { sredA[wid] = v1; sredB[wid] = v2; sredK[wid] = kP; sredK2[wid] = kT; }
        __syncthreads();
        if (w == 0) {
            float s1 = 0.f, s2 = 0.f;
            u64 bP = sredK[0], bT = sredK2[0];
#pragma unroll
            for (int j = 0; j < 16; j++) {
                s1 += sredA[j]; s2 += sredB[j];
                if (j && sredK[j]  > bP) bP = sredK[j];
                if (j && sredK2[j] > bT) bT = sredK2[j];
            }
            atomicAdd(&g_kl_fx, to_fx(s1 * LN2F));   /* log2 -> ln once per block */
            atomicAdd(&g_ew_fx, to_fx(s2));
            atomicMax(&g_pkP[b], bP);
            atomicMax(&g_pkT[b], bT);
            __threadfence();
            atomicAdd(&g_arr1[b], 1u);
            volatile unsigned* a1p = &g_arr1[b];
            while (*a1p < (unsigned)NSEG) __nanosleep(32);
            __threadfence();
        }
    }
    __syncthreads();

    /* ===== PHASE C: EMD-H from smem tile + L2 carry ===== */
    {
        const float* cs = &g_colseg[(b*NSEG)*NW + w];
        float c0 = 0.f, c1 = 0.f, c2 = 0.f, c3 = 0.f;
#pragma unroll
        for (int s2 = 0; s2 < NSEG; s2 += 4) {
            if (s2 + 0 < seg) c0 += cs[(s2+0)*NW];
            if (s2 + 1 < seg) c1 += cs[(s2+1)*NW];
            if (s2 + 2 < seg) c2 += cs[(s2+2)*NW];
            if (s2 + 3 < seg) c3 += cs[(s2+3)*NW];
        }
        float c = (c0 + c1) + (c2 + c3);
        float acc = 0.f;
#pragma unroll
        for (int r = 0; r < SEGROWS; r++) { c += sD[r*SDSTRIDE + skw]; acc += fabsf(c); }

#pragma unroll
        for (int off = 16; off; off >>= 1) acc += __shfl_xor_sync(~0u, acc, off);
        if (lane == 0) sredA[wid] = acc;
        __syncthreads();
        if (w == 0) {
            float s = 0.f;
#pragma unroll
            for (int j = 0; j < 16; j++) s += sredA[j];
            atomicAdd(&g_eh_fx, to_fx(s));
            __threadfence();
            unsigned t = atomicAdd(&g_done, 1u);
            sLast = (t == (unsigned)(NBLK-1)) ? 1 : 0;
        }
    }
    __syncthreads();

    /* ===== FINALIZE: last-done block only ===== */
    if (sLast && w == 0) {
        __threadfence();
        float loss = from_fx(*(volatile u64*)&g_kl_fx) * (1.0f/(float)NB);
        float emd  = (from_fx(*(volatile u64*)&g_ew_fx) + from_fx(*(volatile u64*)&g_eh_fx))
                     * (0.5f / ((float)NB * (float)HWC));
        int cnt = 0;
        for (int bb = 0; bb < NB; bb++) {
            unsigned fp = 0xFFFFFFFFu - (unsigned)(*(volatile u64*)&g_pkP[bb] & 0xFFFFFFFFull);
            unsigned ft = 0xFFFFFFFFu - (unsigned)(*(volatile u64*)&g_pkT[bb] & 0xFFFFFFFFull);
            float ppx = (float)(fp % NW) * (1.0f/511.0f);
            float ppy = (float)(fp / NW) * (1.0f/511.0f);
            float tpx = (float)(ft % NW) * (1.0f/511.0f);
            float tpy = (float)(ft / NW) * (1.0f/511.0f);
            float dx = ppx - tpx, dy = ppy - tpy;
            if (sqrtf(dx*dx + dy*dy) < 0.1f) cnt++;
        }
        float acc = (float)cnt * (1.0f/(float)NB);
        if (out_size > 0) out[0] = loss;
        if (out_size > 1) out[1] = emd;
        if (out_size > 2) out[2] = acc;
        /* reset state for next graph replay */
        g_kl_fx = 0ull; g_ew_fx = 0ull; g_eh_fx = 0ull;
        g_done = 0u;
#pragma unroll
        for (int bb = 0; bb < NB; bb++) {
            g_tsum_fx[bb] = 0ull; g_psum_fx[bb] = 0ull;
            g_pkP[bb] = 0ull;     g_pkT[bb] = 0ull;
            g_arr0[bb] = 0u;      g_arr1[bb] = 0u;
        }
        __threadfence();
    }
}

extern "C" void kernel_launch(void* const* d_in, const int* in_sizes, int n_in,
                              void* d_out, int out_size) {
    const float* pred = (const float*)d_in[0];   /* [8,512,512] */
    const float* pts  = (const float*)d_in[1];   /* [8,32,2]    */
    const float* mask = (const float*)d_in[2];   /* [8]         */
    float* out = (float*)d_out;

    k_all<<<NBLK, 512>>>(pred, pts, mask, out, out_size);
}

// round 16
// speedup vs baseline: 1.0769x; 1.0072x over previous
#include <cuda_runtime.h>
#include <math.h>

#define NB 8
#define NH 512
#define NW 512
#define NP 32
#define HWC (NH*NW)
#define EPSF 1e-8f
#define INV2BW2 50.0f
#define NSEG 32
#define SEGROWS 16
#define SDSTRIDE 544        /* >= 512 + 32 skew: max skewed index 542 */
#define NBLK (NB*NSEG)      /* 256 */
#define LN2F 0.6931471805599453f

typedef unsigned long long u64;

/* ---------------- scratch (device globals) ---------------- */
__device__ float g_ex[NB*NP*NW];
__device__ float g_ey[NB*NP*NH];
__device__ float g_colseg[NB*NSEG*NW];   /* 512 KB, L2-resident */
__device__ u64 g_tsum_fx[NB];            /* fixed-point 2^32 accumulators */
__device__ u64 g_psum_fx[NB];
__device__ u64 g_kl_fx, g_ew_fx, g_eh_fx;
__device__ u64 g_pkP[NB], g_pkT[NB];     /* packed argmax keys */
__device__ unsigned g_arr0[NB], g_arr1[NB], g_done;

/* fixed-point (scale 2^32), exact integer atomics -> deterministic */
__device__ __forceinline__ u64 to_fx(float x) {
    return (u64)__double2ll_rn((double)x * 4294967296.0);
}
__device__ __forceinline__ float from_fx(u64 v) {
    return (float)((double)(long long)v * (1.0/4294967296.0));
}

/* packed f32x2 ops (Blackwell) */
__device__ __forceinline__ u64 fma2(u64 a, u64 b, u64 c) {
    u64 d; asm("fma.rn.f32x2 %0, %1, %2, %3;" : "=l"(d) : "l"(a), "l"(b), "l"(c)); return d;
}
__device__ __forceinline__ u64 add2(u64 a, u64 b) {
    u64 d; asm("add.rn.f32x2 %0, %1, %2;" : "=l"(d) : "l"(a), "l"(b)); return d;
}
__device__ __forceinline__ u64 pack2(float lo, float hi) {
    u64 d; asm("mov.b64 %0, {%1, %2};" : "=l"(d) : "f"(lo), "f"(hi)); return d;
}
__device__ __forceinline__ float hadd2(u64 v) {
    float lo, hi; asm("mov.b64 {%0, %1}, %2;" : "=f"(lo), "=f"(hi) : "l"(v)); return lo + hi;
}

/* argmax key: val>=0 so float bits monotone; ~fid gives min-idx tie-break */
__device__ __forceinline__ u64 mkkey(float v, int fid) {
    return ((u64)__float_as_uint(v) << 32) | (u64)(0xFFFFFFFFu - (unsigned)fid);
}

__global__ __launch_bounds__(512, 2) void k_all(const float* __restrict__ pred,
                                                const float* __restrict__ pts,
                                                const float* __restrict__ mask,
                                                float* __restrict__ out, int out_size) {
    int blk = blockIdx.x;                 /* b*NSEG+seg == factor index b*NP+n */
    int b = blk >> 5, seg = blk & 31;
    int w = threadIdx.x, lane = w & 31, wid = w >> 5;

    __shared__ __align__(16) float sEy[SEGROWS*NP];
    __shared__ float sD[SEGROWS*SDSTRIDE];
    __shared__ float sredA[16], sredB[16], sredC[16];
    __shared__ u64   sredK[16], sredK2[16];
    __shared__ float sNorm[4];            /* mInvSp, cSp, mInvSt, cSt */
    __shared__ int   sLast;

    /* ===== PHASE A: factors + 1-D sums + own-tile psum; pred tile -> sD ===== */
    {
        const float4* p4 = (const float4*)(pred + (b*NH + seg*SEGROWS)*NW);
        float4 q0 = p4[w], q1 = p4[w+512], q2 = p4[w+1024], q3 = p4[w+1536];

        float px = pts[blk*2 + 0];
        float py = pts[blk*2 + 1];
        float c  = (float)w * (1.0f/511.0f);
        float dx = c - px, dy = c - py;
        float ex = __expf(-dx*dx*INV2BW2);
        float ey = __expf(-dy*dy*INV2BW2);
        g_ex[blk*NW + w] = ex;
        g_ey[blk*NH + w] = ey;

        /* stage pred tile into sD with the SAME skew phase B uses.
           thread holds rows r0+{0,4,8,12}, cols c4..c4+3; skew(c4+j) is
           contiguous in j since c4 % 16 in {0,4,8,12}. */
        {
            int c4 = (w & 127) << 2;
            int r0 = w >> 7;
            int sk4 = c4 + (c4 >> 4);
            float* d0 = &sD[(r0 +  0)*SDSTRIDE + sk4];
            float* d1 = &sD[(r0 +  4)*SDSTRIDE + sk4];
            float* d2 = &sD[(r0 +  8)*SDSTRIDE + sk4];
            float* d3 = &sD[(r0 + 12)*SDSTRIDE + sk4];
            d0[0]=q0.x; d0[1]=q0.y; d0[2]=q0.z; d0[3]=q0.w;
            d1[0]=q1.x; d1[1]=q1.y; d1[2]=q1.z; d1[3]=q1.w;
            d2[0]=q2.x; d2[1]=q2.y; d2[2]=q2.z; d2[3]=q2.w;
            d3[0]=q3.x; d3[1]=q3.y; d3[2]=q3.z; d3[3]=q3.w;
        }

        float ps = ((q0.x+q0.y)+(q0.z+q0.w)) + ((q1.x+q1.y)+(q1.z+q1.w))
                 + ((q2.x+q2.y)+(q2.z+q2.w)) + ((q3.x+q3.y)+(q3.z+q3.w));
        float vx = ex, vy = ey;
#pragma unroll
        for (int off = 16; off; off >>= 1) {
            vx += __shfl_xor_sync(~0u, vx, off);
            vy += __shfl_xor_sync(~0u, vy, off);
            ps += __shfl_xor_sync(~0u, ps, off);
        }
        if (lane == 0) { sredA[wid] = vx; sredB[wid] = vy; sredC[wid] = ps; }
        __syncthreads();
        if (w == 0) {
            float sx = 0.f, sy = 0.f, sp = 0.f;
#pragma unroll
            for (int j = 0; j < 16; j++) { sx += sredA[j]; sy += sredB[j]; sp += sredC[j]; }
            atomicAdd(&g_tsum_fx[b], to_fx(sx * sy));
            atomicAdd(&g_psum_fx[b], to_fx(sp));
            __threadfence();
            atomicAdd(&g_arr0[b], 1u);
            volatile unsigned* a0 = &g_arr0[b];
            while (*a0 < (unsigned)NSEG) __nanosleep(32);
            __threadfence();
            float ts = from_fx(*(volatile u64*)&g_tsum_fx[b]);
            float pp = from_fx(*(volatile u64*)&g_psum_fx[b]);
            float mm = mask[b];
            float iSp = 1.0f / (mm*pp + (float)HWC*EPSF);
            float iSt = 1.0f / (mm*ts + (float)HWC*EPSF);
            sNorm[0] = mm * iSp;   sNorm[1] = EPSF * iSp;
            sNorm[2] = mm * iSt;   sNorm[3] = EPSF * iSt;
        }
    }
    __syncthreads();

    /* ===== PHASE B: density(FFMA2) + KL(log2) + EMD-W + colseg + argmax ===== */
    sEy[(w >> 5)*NP + (w & 31)] = g_ey[(b*NP + (w & 31))*NH + seg*SEGROWS + (w >> 5)];

    u64 rexp[NP/2];
#pragma unroll
    for (int n = 0; n < NP; n += 2)
        rexp[n >> 1] = pack2(g_ex[(b*NP + n)*NW + w], g_ex[(b*NP + n + 1)*NW + w]);
    __syncthreads();

    float mInvSp = sNorm[0], cSp = sNorm[1];
    float mInvSt = sNorm[2], cSt = sNorm[3];

    float klacc = 0.f, ccol = 0.f;      /* klacc accumulated in log2 domain */
    float apv = -1e30f, atv = -1e30f;
    int   api = 0, ati = 0;
    int fid0 = seg*SEGROWS*NW + w;
    int skw = w + (w >> 4);

#pragma unroll 2
    for (int r = 0; r < SEGROWS; r++) {
        float p = sD[r*SDSTRIDE + skw];           /* pred from smem (29 cyc) */
        u64 a0 = 0ull, a1 = 0ull;
#pragma unroll
        for (int q = 0; q < NP/4; q++) {
            ulonglong2 e = *(const ulonglong2*)&sEy[r*NP + q*4];
            a0 = fma2(e.x, rexp[q*2 + 0], a0);
            a1 = fma2(e.y, rexp[q*2 + 1], a1);
        }
        float acc = hadd2(add2(a0, a1));
        float pn = fmaf(p,   mInvSp, cSp);
        float tn = fmaf(acc, mInvSt, cSt);
        float d  = pn - tn;
        sD[r*SDSTRIDE + skw] = d;                 /* overwrite own slot */
        klacc = fmaf(tn, __log2f(__fdividef(tn, pn + EPSF)), klacc);
        ccol += d;
        int fid = fid0 + r*NW;
        if (pn > apv) { apv = pn; api = fid; }
        if (tn > atv) { atv = tn; ati = fid; }
    }
    g_colseg[blk*NW + w] = ccol;
    __syncthreads();

    /* EMD-W: warp wid scans row wid; lane owns 16 contiguous elems */
    float ewacc = 0.f;
    {
        float vals[16];
        int base = wid*SDSTRIDE + lane*17;
        float s = 0.f;
#pragma unroll
        for (int i = 0; i < 16; i++) { vals[i] = sD[base + i]; s += vals[i]; }
        float incl = s;
#pragma unroll
        for (int off = 1; off < 32; off <<= 1) {
            float u = __shfl_up_sync(~0u, incl, off);
            if (lane >= off) incl += u;
        }
        float run = incl - s;
#pragma unroll
        for (int i = 0; i < 16; i++) { run += vals[i]; ewacc += fabsf(run); }
    }

    /* block reductions: kl + emdw (floats) + both argmax keys (u64), one pass */
    {
        float v1 = klacc, v2 = ewacc;
        u64 kP = mkkey(apv, api), kT = mkkey(atv, ati);
#pragma unroll
        for (int off = 16; off; off >>= 1) {
            v1 += __shfl_xor_sync(~0u, v1, off);
            v2 += __shfl_xor_sync(~0u, v2, off);
            u64 oP = __shfl_xor_sync(~0u, kP, off);
            u64 oT = __shfl_xor_sync(~0u, kT, off);
            if (oP > kP) kP = oP;
            if (oT > kT) kT = oT;
        }
        if (lane == 0) { sredA[wid] = v1; sredB[wid] = v2; sredK[wid] = kP; sredK2[wid] = kT; }
        __syncthreads();
        if (w == 0) {
            float s1 = 0.f, s2 = 0.f;
            u64 bP = sredK[0], bT = sredK2[0];
#pragma unroll
            for (int j = 0; j < 16; j++) {
                s1 += sredA[j]; s2 += sredB[j];
                if (j && sredK[j]  > bP) bP = sredK[j];
                if (j && sredK2[j] > bT) bT = sredK2[j];
            }
            atomicAdd(&g_kl_fx, to_fx(s1 * LN2F));   /* log2 -> ln once per block */
            atomicAdd(&g_ew_fx, to_fx(s2));
            atomicMax(&g_pkP[b], bP);
            atomicMax(&g_pkT[b], bT);
            __threadfence();
            atomicAdd(&g_arr1[b], 1u);
            volatile unsigned* a1p = &g_arr1[b];
            while (*a1p < (unsigned)NSEG) __nanosleep(32);
            __threadfence();
        }
    }
    __syncthreads();

    /* ===== PHASE C: EMD-H from smem tile + L2 carry ===== */
    {
        const float* cs = &g_colseg[(b*NSEG)*NW + w];
        float c0 = 0.f, c1 = 0.f, c2 = 0.f, c3 = 0.f;
#pragma unroll
        for (int s2 = 0; s2 < NSEG; s2 += 4) {
            if (s2 + 0 < seg) c0 += cs[(s2+0)*NW];
            if (s2 + 1 < seg) c1 += cs[(s2+1)*NW];
            if (s2 + 2 < seg) c2 += cs[(s2+2)*NW];
            if (s2 + 3 < seg) c3 += cs[(s2+3)*NW];
        }
        float c = (c0 + c1) + (c2 + c3);
        float acc = 0.f;
#pragma unroll
        for (int r = 0; r < SEGROWS; r++) { c += sD[r*SDSTRIDE + skw]; acc += fabsf(c); }

#pragma unroll
        for (int off = 16; off; off >>= 1) acc += __shfl_xor_sync(~0u, acc, off);
        if (lane == 0) sredA[wid] = acc;
        __syncthreads();
        if (w == 0) {
            float s = 0.f;
#pragma unroll
            for (int j = 0; j < 16; j++) s += sredA[j];
            atomicAdd(&g_eh_fx, to_fx(s));
            __threadfence();
            unsigned t = atomicAdd(&g_done, 1u);
            sLast = (t == (unsigned)(NBLK-1)) ? 1 : 0;
        }
    }
    __syncthreads();

    /* ===== FINALIZE: last-done block only ===== */
    if (sLast && w == 0) {
        __threadfence();
        float loss = from_fx(*(volatile u64*)&g_kl_fx) * (1.0f/(float)NB);
        float emd  = (from_fx(*(volatile u64*)&g_ew_fx) + from_fx(*(volatile u64*)&g_eh_fx))
                     * (0.5f / ((float)NB * (float)HWC));
        int cnt = 0;
        for (int bb = 0; bb < NB; bb++) {
            unsigned fp = 0xFFFFFFFFu - (unsigned)(*(volatile u64*)&g_pkP[bb] & 0xFFFFFFFFull);
            unsigned ft = 0xFFFFFFFFu - (unsigned)(*(volatile u64*)&g_pkT[bb] & 0xFFFFFFFFull);
            float ppx = (float)(fp % NW) * (1.0f/511.0f);
            float ppy = (float)(fp / NW) * (1.0f/511.0f);
            float tpx = (float)(ft % NW) * (1.0f/511.0f);
            float tpy = (float)(ft / NW) * (1.0f/511.0f);
            float dx = ppx - tpx, dy = ppy - tpy;
            if (sqrtf(dx*dx + dy*dy) < 0.1f) cnt++;
        }
        float acc = (float)cnt * (1.0f/(float)NB);
        if (out_size > 0) out[0] = loss;
        if (out_size > 1) out[1] = emd;
        if (out_size > 2) out[2] = acc;
        /* reset state for next graph replay */
        g_kl_fx = 0ull; g_ew_fx = 0ull; g_eh_fx = 0ull;
        g_done = 0u;
#pragma unroll
        for (int bb = 0; bb < NB; bb++) {
            g_tsum_fx[bb] = 0ull; g_psum_fx[bb] = 0ull;
            g_pkP[bb] = 0ull;     g_pkT[bb] = 0ull;
            g_arr0[bb] = 0u;      g_arr1[bb] = 0u;
        }
        __threadfence();
    }
}

extern "C" void kernel_launch(void* const* d_in, const int* in_sizes, int n_in,
                              void* d_out, int out_size) {
    const float* pred = (const float*)d_in[0];   /* [8,512,512] */
    const float* pts  = (const float*)d_in[1];   /* [8,32,2]    */
    const float* mask = (const float*)d_in[2];   /* [8]         */
    float* out = (float*)d_out;

    k_all<<<NBLK, 512>>>(pred, pts, mask, out, out_size);
}

// round 17
// speedup vs baseline: 1.1636x; 1.0805x over previous
#include <cuda_runtime.h>
#include <math.h>

#define NB 8
#define NH 512
#define NW 512
#define NP 32
#define HWC (NH*NW)
#define EPSF 1e-8f
#define INV2BW2 50.0f
#define NSEG 32
#define SEGROWS 16
#define SDSTRIDE 544        /* >= 512 + 32 skew: max skewed index 542 */
#define NBLK (NB*NSEG)      /* 256 */
#define LN2F 0.6931471805599453f

typedef unsigned long long u64;

/* ---------------- scratch (device globals) ---------------- */
__device__ float g_ex[NB*NP*NW];
__device__ float g_ey[NB*NP*NH];
__device__ float g_colseg[NB*NSEG*NW];   /* 512 KB, L2-resident */
__device__ u64 g_tsum_fx[NB];            /* fixed-point 2^32 accumulators */
__device__ u64 g_psum_fx[NB];
__device__ u64 g_kl_fx, g_ew_fx, g_eh_fx;
__device__ u64 g_pkP[NB], g_pkT[NB];     /* packed argmax keys */
__device__ unsigned g_arr0[NB];          /* phase-A rendezvous (normalizers) */
__device__ unsigned g_rdy[NB];           /* colseg readiness bitmask per batch */
__device__ unsigned g_done;

/* fixed-point (scale 2^32), exact integer atomics -> deterministic */
__device__ __forceinline__ u64 to_fx(float x) {
    return (u64)__double2ll_rn((double)x * 4294967296.0);
}
__device__ __forceinline__ float from_fx(u64 v) {
    return (float)((double)(long long)v * (1.0/4294967296.0));
}

/* packed f32x2 ops (Blackwell) */
__device__ __forceinline__ u64 fma2(u64 a, u64 b, u64 c) {
    u64 d; asm("fma.rn.f32x2 %0, %1, %2, %3;" : "=l"(d) : "l"(a), "l"(b), "l"(c)); return d;
}
__device__ __forceinline__ u64 add2(u64 a, u64 b) {
    u64 d; asm("add.rn.f32x2 %0, %1, %2;" : "=l"(d) : "l"(a), "l"(b)); return d;
}
__device__ __forceinline__ u64 pack2(float lo, float hi) {
    u64 d; asm("mov.b64 %0, {%1, %2};" : "=l"(d) : "f"(lo), "f"(hi)); return d;
}
__device__ __forceinline__ float hadd2(u64 v) {
    float lo, hi; asm("mov.b64 {%0, %1}, %2;" : "=f"(lo), "=f"(hi) : "l"(v)); return lo + hi;
}

/* argmax key: val>=0 so float bits monotone; ~fid gives min-idx tie-break */
__device__ __forceinline__ u64 mkkey(float v, int fid) {
    return ((u64)__float_as_uint(v) << 32) | (u64)(0xFFFFFFFFu - (unsigned)fid);
}

__global__ __launch_bounds__(512, 2) void k_all(const float* __restrict__ pred,
                                                const float* __restrict__ pts,
                                                const float* __restrict__ mask,
                                                float* __restrict__ out, int out_size) {
    int blk = blockIdx.x;                 /* b*NSEG+seg == factor index b*NP+n */
    int b = blk >> 5, seg = blk & 31;
    int w = threadIdx.x, lane = w & 31, wid = w >> 5;

    __shared__ __align__(16) float sEy[SEGROWS*NP];
    __shared__ float sD[SEGROWS*SDSTRIDE];
    __shared__ float sredA[16], sredB[16], sredC[16];
    __shared__ u64   sredK[16], sredK2[16];
    __shared__ float sNorm[4];            /* mInvSp, cSp, mInvSt, cSt */
    __shared__ int   sLast;

    /* ===== PHASE A: factors + 1-D sums + own-tile psum; pred tile -> sD ===== */
    {
        const float4* p4 = (const float4*)(pred + (b*NH + seg*SEGROWS)*NW);
        float4 q0 = p4[w], q1 = p4[w+512], q2 = p4[w+1024], q3 = p4[w+1536];

        float px = pts[blk*2 + 0];
        float py = pts[blk*2 + 1];
        float c  = (float)w * (1.0f/511.0f);
        float dx = c - px, dy = c - py;
        float ex = __expf(-dx*dx*INV2BW2);
        float ey = __expf(-dy*dy*INV2BW2);
        g_ex[blk*NW + w] = ex;
        g_ey[blk*NH + w] = ey;

        /* stage pred tile into sD with the SAME skew phase B uses */
        {
            int c4 = (w & 127) << 2;
            int r0 = w >> 7;
            int sk4 = c4 + (c4 >> 4);
            float* d0 = &sD[(r0 +  0)*SDSTRIDE + sk4];
            float* d1 = &sD[(r0 +  4)*SDSTRIDE + sk4];
            float* d2 = &sD[(r0 +  8)*SDSTRIDE + sk4];
            float* d3 = &sD[(r0 + 12)*SDSTRIDE + sk4];
            d0[0]=q0.x; d0[1]=q0.y; d0[2]=q0.z; d0[3]=q0.w;
            d1[0]=q1.x; d1[1]=q1.y; d1[2]=q1.z; d1[3]=q1.w;
            d2[0]=q2.x; d2[1]=q2.y; d2[2]=q2.z; d2[3]=q2.w;
            d3[0]=q3.x; d3[1]=q3.y; d3[2]=q3.z; d3[3]=q3.w;
        }

        float ps = ((q0.x+q0.y)+(q0.z+q0.w)) + ((q1.x+q1.y)+(q1.z+q1.w))
                 + ((q2.x+q2.y)+(q2.z+q2.w)) + ((q3.x+q3.y)+(q3.z+q3.w));
        float vx = ex, vy = ey;
#pragma unroll
        for (int off = 16; off; off >>= 1) {
            vx += __shfl_xor_sync(~0u, vx, off);
            vy += __shfl_xor_sync(~0u, vy, off);
            ps += __shfl_xor_sync(~0u, ps, off);
        }
        if (lane == 0) { sredA[wid] = vx; sredB[wid] = vy; sredC[wid] = ps; }
        __syncthreads();
        if (w == 0) {
            float sx = 0.f, sy = 0.f, sp = 0.f;
#pragma unroll
            for (int j = 0; j < 16; j++) { sx += sredA[j]; sy += sredB[j]; sp += sredC[j]; }
            atomicAdd(&g_tsum_fx[b], to_fx(sx * sy));
            atomicAdd(&g_psum_fx[b], to_fx(sp));
            __threadfence();
            atomicAdd(&g_arr0[b], 1u);
            volatile unsigned* a0 = &g_arr0[b];
            while (*a0 < (unsigned)NSEG) __nanosleep(32);
            __threadfence();
            float ts = from_fx(*(volatile u64*)&g_tsum_fx[b]);
            float pp = from_fx(*(volatile u64*)&g_psum_fx[b]);
            float mm = mask[b];
            float iSp = 1.0f / (mm*pp + (float)HWC*EPSF);
            float iSt = 1.0f / (mm*ts + (float)HWC*EPSF);
            sNorm[0] = mm * iSp;   sNorm[1] = EPSF * iSp;
            sNorm[2] = mm * iSt;   sNorm[3] = EPSF * iSt;
        }
    }
    __syncthreads();

    /* ===== PHASE B: density(FFMA2) + KL(2 indep log2) + EMD-W + colseg + argmax ===== */
    sEy[(w >> 5)*NP + (w & 31)] = g_ey[(b*NP + (w & 31))*NH + seg*SEGROWS + (w >> 5)];

    u64 rexp[NP/2];
#pragma unroll
    for (int n = 0; n < NP; n += 2)
        rexp[n >> 1] = pack2(g_ex[(b*NP + n)*NW + w], g_ex[(b*NP + n + 1)*NW + w]);
    __syncthreads();

    float mInvSp = sNorm[0], cSp = sNorm[1];
    float mInvSt = sNorm[2], cSt = sNorm[3];

    float klacc = 0.f, ccol = 0.f;      /* klacc accumulated in log2 domain */
    float apv = -1e30f, atv = -1e30f;
    int   api = 0, ati = 0;
    int fid0 = seg*SEGROWS*NW + w;
    int skw = w + (w >> 4);

#pragma unroll 2
    for (int r = 0; r < SEGROWS; r++) {
        float p = sD[r*SDSTRIDE + skw];           /* pred from smem */
        u64 a0 = 0ull, a1 = 0ull;
#pragma unroll
        for (int q = 0; q < NP/4; q++) {
            ulonglong2 e = *(const ulonglong2*)&sEy[r*NP + q*4];
            a0 = fma2(e.x, rexp[q*2 + 0], a0);
            a1 = fma2(e.y, rexp[q*2 + 1], a1);
        }
        float acc = hadd2(add2(a0, a1));
        float pn = fmaf(p,   mInvSp, cSp);
        float tn = fmaf(acc, mInvSt, cSt);
        float d  = pn - tn;
        sD[r*SDSTRIDE + skw] = d;                 /* overwrite own slot */
        klacc = fmaf(tn, __log2f(tn) - __log2f(pn + EPSF), klacc);
        ccol += d;
        int fid = fid0 + r*NW;
        if (pn > apv) { apv = pn; api = fid; }
        if (tn > atv) { atv = tn; ati = fid; }
    }
    g_colseg[blk*NW + w] = ccol;
    __syncthreads();
    /* publish colseg readiness EARLY: siblings can enter phase C while this
       block still does its EMD-W scan + reductions. */
    if (w == 0) {
        __threadfence();
        atomicOr(&g_rdy[b], 1u << seg);
    }

    /* EMD-W: warp wid scans row wid; lane owns 16 contiguous elems */
    float ewacc = 0.f;
    {
        float vals[16];
        int base = wid*SDSTRIDE + lane*17;
        float s = 0.f;
#pragma unroll
        for (int i = 0; i < 16; i++) { vals[i] = sD[base + i]; s += vals[i]; }
        float incl = s;
#pragma unroll
        for (int off = 1; off < 32; off <<= 1) {
            float u = __shfl_up_sync(~0u, incl, off);
            if (lane >= off) incl += u;
        }
        float run = incl - s;
#pragma unroll
        for (int i = 0; i < 16; i++) { run += vals[i]; ewacc += fabsf(run); }
    }

    /* block reductions: kl + emdw (floats) + both argmax keys (u64), one pass */
    {
        float v1 = klacc, v2 = ewacc;
        u64 kP = mkkey(apv, api), kT = mkkey(atv, ati);
#pragma unroll
        for (int off = 16; off; off >>= 1) {
            v1 += __shfl_xor_sync(~0u, v1, off);
            v2 += __shfl_xor_sync(~0u, v2, off);
            u64 oP = __shfl_xor_sync(~0u, kP, off);
            u64 oT = __shfl_xor_sync(~0u, kT, off);
            if (oP > kP) kP = oP;
            if (oT > kT) kT = oT;
        }
        if (lane == 0) { sredA[wid] = v1; sredB[wid] = v2; sredK[wid] = kP; sredK2[wid] = kT; }
        __syncthreads();
        if (w == 0) {
            float s1 = 0.f, s2 = 0.f;
            u64 bP = sredK[0], bT = sredK2[0];
#pragma unroll
            for (int j = 0; j < 16; j++) {
                s1 += sredA[j]; s2 += sredB[j];
                if (j && sredK[j]  > bP) bP = sredK[j];
                if (j && sredK2[j] > bT) bT = sredK2[j];
            }
            atomicAdd(&g_kl_fx, to_fx(s1 * LN2F));   /* log2 -> ln once per block */
            atomicAdd(&g_ew_fx, to_fx(s2));
            atomicMax(&g_pkP[b], bP);
            atomicMax(&g_pkT[b], bT);
        }
    }

    /* ===== PHASE C: wait only for prefix siblings' colseg, then EMD-H ===== */
    {
        if (w == 0 && seg > 0) {
            unsigned need = (1u << seg) - 1u;
            volatile unsigned* rp = &g_rdy[b];
            while ((*rp & need) != need) __nanosleep(32);
            __threadfence();
        }
        __syncthreads();

        const float* cs = &g_colseg[(b*NSEG)*NW + w];
        float c0 = 0.f, c1 = 0.f, c2 = 0.f, c3 = 0.f;
#pragma unroll
        for (int s2 = 0; s2 < NSEG; s2 += 4) {
            if (s2 + 0 < seg) c0 += cs[(s2+0)*NW];
            if (s2 + 1 < seg) c1 += cs[(s2+1)*NW];
            if (s2 + 2 < seg) c2 += cs[(s2+2)*NW];
            if (s2 + 3 < seg) c3 += cs[(s2+3)*NW];
        }
        float c = (c0 + c1) + (c2 + c3);
        float acc = 0.f;
#pragma unroll
        for (int r = 0; r < SEGROWS; r++) { c += sD[r*SDSTRIDE + skw]; acc += fabsf(c); }

#pragma unroll
        for (int off = 16; off; off >>= 1) acc += __shfl_xor_sync(~0u, acc, off);
        if (lane == 0) sredA[wid] = acc;
        __syncthreads();
        if (w == 0) {
            float s = 0.f;
#pragma unroll
            for (int j = 0; j < 16; j++) s += sredA[j];
            atomicAdd(&g_eh_fx, to_fx(s));
            __threadfence();      /* order ALL this block's atomics before g_done */
            unsigned t = atomicAdd(&g_done, 1u);
            sLast = (t == (unsigned)(NBLK-1)) ? 1 : 0;
        }
    }
    __syncthreads();

    /* ===== FINALIZE: last-done block only ===== */
    if (sLast && w == 0) {
        __threadfence();
        float loss = from_fx(*(volatile u64*)&g_kl_fx) * (1.0f/(float)NB);
        float emd  = (from_fx(*(volatile u64*)&g_ew_fx) + from_fx(*(volatile u64*)&g_eh_fx))
                     * (0.5f / ((float)NB * (float)HWC));
        int cnt = 0;
        for (int bb = 0; bb < NB; bb++) {
            unsigned fp = 0xFFFFFFFFu - (unsigned)(*(volatile u64*)&g_pkP[bb] & 0xFFFFFFFFull);
            unsigned ft = 0xFFFFFFFFu - (unsigned)(*(volatile u64*)&g_pkT[bb] & 0xFFFFFFFFull);
            float ppx = (float)(fp % NW) * (1.0f/511.0f);
            float ppy = (float)(fp / NW) * (1.0f/511.0f);
            float tpx = (float)(ft % NW) * (1.0f/511.0f);
            float tpy = (float)(ft / NW) * (1.0f/511.0f);
            float dx = ppx - tpx, dy = ppy - tpy;
            if (sqrtf(dx*dx + dy*dy) < 0.1f) cnt++;
        }
        float acc = (float)cnt * (1.0f/(float)NB);
        if (out_size > 0) out[0] = loss;
        if (out_size > 1) out[1] = emd;
        if (out_size > 2) out[2] = acc;
        /* reset state for next graph replay */
        g_kl_fx = 0ull; g_ew_fx = 0ull; g_eh_fx = 0ull;
        g_done = 0u;
#pragma unroll
        for (int bb = 0; bb < NB; bb++) {
            g_tsum_fx[bb] = 0ull; g_psum_fx[bb] = 0ull;
            g_pkP[bb] = 0ull;     g_pkT[bb] = 0ull;
            g_arr0[bb] = 0u;      g_rdy[bb] = 0u;
        }
        __threadfence();
    }
}

extern "C" void kernel_launch(void* const* d_in, const int* in_sizes, int n_in,
                              void* d_out, int out_size) {
    const float* pred = (const float*)d_in[0];   /* [8,512,512] */
    const float* pts  = (const float*)d_in[1];   /* [8,32,2]    */
    const float* mask = (const float*)d_in[2];   /* [8]         */
    float* out = (float*)d_out;

    k_all<<<NBLK, 512>>>(pred, pts, mask, out, out_size);
}